// round 1
// baseline (speedup 1.0000x reference)
#include <cuda_runtime.h>
#include <math.h>

#define NB     32
#define SEQ    240
#define HID    1024
#define NLAYER 8
#define NHEAD  16
#define DHEAD  64
#define NVOCAB 48
#define BS_TOT (NB*SEQ)   // 7680

// ---------------- device scratch (no allocation allowed) ----------------
__device__ float g_z  [BS_TOT*HID];
__device__ float g_q  [BS_TOT*HID];
__device__ float g_k  [BS_TOT*HID];
__device__ float g_v  [BS_TOT*HID];
__device__ float g_att[BS_TOT*HID];   // attention out, later reused for FFN out
__device__ float g_z1 [BS_TOT*HID];
__device__ float g_ffh[BS_TOT*HID];
__device__ float g_sc [NB*NHEAD*SEQ*SEQ];   // 118 MB scores/probs
__device__ float g_pool[NB*HID];

// ---------------- embedding: argmax + gather + posenc ----------------
__global__ void embed_kernel(const float* __restrict__ x,
                             const float* __restrict__ w_emb,
                             const float* __restrict__ p_emb,
                             const int*   __restrict__ lengths) {
    int bs = blockIdx.x;
    int b = bs / SEQ, s = bs % SEQ;
    __shared__ int s_tok;
    int tid = threadIdx.x;
    if (tid < 32) {
        const float* xp = x + (long long)bs * NVOCAB;
        float bv = -1e30f; int bi = 0;
        for (int c = tid; c < NVOCAB; c += 32) {
            float v = xp[c];
            if (v > bv) { bv = v; bi = c; }
        }
        for (int off = 16; off > 0; off >>= 1) {
            float ov = __shfl_down_sync(0xffffffff, bv, off);
            int   oi = __shfl_down_sync(0xffffffff, bi, off);
            if (ov > bv || (ov == bv && oi < bi)) { bv = ov; bi = oi; }
        }
        if (tid == 0) s_tok = bi;
    }
    __syncthreads();
    int tok = s_tok;
    float valid = (s < lengths[b]) ? 1.0f : 0.0f;
    const float* we = w_emb + (long long)tok * HID;
    const float* pe = p_emb + (long long)s * HID;
    float* zp = g_z + (long long)bs * HID;
    for (int h = tid; h < HID; h += blockDim.x)
        zp[h] = we[h] * valid + pe[h];
}

// ---------------- fp32 SGEMM: C[M,N] = A[M,K] @ W[K,N] + bias, optional GELU ----------------
// M = 7680, N = K = 1024.  128x128 tile, BK=8, 256 threads, 8x8 per thread.
template<int ACT>
__global__ __launch_bounds__(256, 2)
void sgemm_bias(const float* __restrict__ A, const float* __restrict__ W,
                const float* __restrict__ bias, float* __restrict__ C) {
    __shared__ float As[8][128];
    __shared__ float Bs[8][128];
    int tid = threadIdx.x;
    int tx = tid & 15, ty = tid >> 4;
    int row0 = blockIdx.y * 128;
    int col0 = blockIdx.x * 128;

    float acc[8][8];
#pragma unroll
    for (int i = 0; i < 8; i++)
#pragma unroll
        for (int j = 0; j < 8; j++) acc[i][j] = 0.f;

    int aRow = tid >> 1;          // 0..127
    int aK   = (tid & 1) * 4;     // 0 or 4
    int bK   = tid >> 5;          // 0..7
    int bCol = (tid & 31) * 4;    // 0..124
    const float* Aptr = A + (long long)(row0 + aRow) * HID + aK;
    const float* Wptr = W + (long long)bK * HID + col0 + bCol;

    for (int k0 = 0; k0 < HID; k0 += 8) {
        float4 a = *(const float4*)(Aptr + k0);
        As[aK+0][aRow] = a.x; As[aK+1][aRow] = a.y;
        As[aK+2][aRow] = a.z; As[aK+3][aRow] = a.w;
        float4 bvec = *(const float4*)(Wptr + (long long)k0 * HID);
        *(float4*)&Bs[bK][bCol] = bvec;
        __syncthreads();
#pragma unroll
        for (int kk = 0; kk < 8; kk++) {
            float ar[8], br[8];
            *(float4*)&ar[0] = *(const float4*)&As[kk][ty*8];
            *(float4*)&ar[4] = *(const float4*)&As[kk][ty*8+4];
            *(float4*)&br[0] = *(const float4*)&Bs[kk][tx*8];
            *(float4*)&br[4] = *(const float4*)&Bs[kk][tx*8+4];
#pragma unroll
            for (int i = 0; i < 8; i++)
#pragma unroll
                for (int j = 0; j < 8; j++)
                    acc[i][j] += ar[i] * br[j];
        }
        __syncthreads();
    }

#pragma unroll
    for (int i = 0; i < 8; i++) {
        int r = row0 + ty*8 + i;
#pragma unroll
        for (int j4 = 0; j4 < 2; j4++) {
            float4 o;
            float* op = &o.x;
#pragma unroll
            for (int j = 0; j < 4; j++) {
                int c = col0 + tx*8 + j4*4 + j;
                float v = acc[i][j4*4+j] + bias[c];
                if (ACT == 1) v = 0.5f * v * (1.0f + erff(v * 0.70710678118654752f));
                op[j] = v;
            }
            *(float4*)&C[(long long)r * HID + col0 + tx*8 + j4*4] = o;
        }
    }
}

// ---------------- attention scores: Q @ K^T * scale, causal tiles only ----------------
__global__ void scores_kernel(const float* __restrict__ q, const float* __restrict__ k) {
    int kt = blockIdx.x, qt = blockIdx.y;
    if (kt > qt) return;
    int bh = blockIdx.z;
    int b = bh / NHEAD, h = bh % NHEAD;
    __shared__ float Qs[16][68];
    __shared__ float Ks[16][68];
    int tid = threadIdx.x;
    {   // load 16x64 each, one float4 per thread
        int row = tid >> 4, c4 = (tid & 15) * 4;
        const float* qg = q + ((long long)(b*SEQ + qt*16 + row) * HID) + h*DHEAD + c4;
        const float* kg = k + ((long long)(b*SEQ + kt*16 + row) * HID) + h*DHEAD + c4;
        *(float4*)&Qs[row][c4] = *(const float4*)qg;
        *(float4*)&Ks[row][c4] = *(const float4*)kg;
    }
    __syncthreads();
    int ty = tid >> 4, tx = tid & 15;
    float acc = 0.f;
#pragma unroll
    for (int d4 = 0; d4 < 16; d4++) {
        float4 qa = *(const float4*)&Qs[ty][d4*4];
        float4 ka = *(const float4*)&Ks[tx][d4*4];
        acc += qa.x*ka.x + qa.y*ka.y + qa.z*ka.z + qa.w*ka.w;
    }
    int qg = qt*16 + ty, kg = kt*16 + tx;
    float out = (kg <= qg) ? acc * (1.0f/32.0f) : 0.0f;
    g_sc[((long long)bh * SEQ + qg) * SEQ + kg] = out;
}

// ---------------- softmax per row (causal length q+1), padded query rows -> 0 ----------------
__global__ void softmax_kernel(const int* __restrict__ lengths) {
    int warp = threadIdx.x >> 5;
    int lane = threadIdx.x & 31;
    long long row = (long long)blockIdx.x * 8 + warp;
    int bh = (int)(row / SEQ);
    int qi = (int)(row % SEQ);
    int b = bh / NHEAD;
    float* p = g_sc + row * SEQ;
    int len = lengths[b];
    if (qi >= len) {
        for (int kk = lane; kk < SEQ; kk += 32) p[kk] = 0.f;
        return;
    }
    int n = qi + 1;
    float vals[8];
    int cnt = 0;
    float m = -1e30f;
    for (int kk = lane; kk < n; kk += 32) {
        vals[cnt] = p[kk];
        m = fmaxf(m, vals[cnt]);
        cnt++;
    }
    for (int off = 16; off > 0; off >>= 1)
        m = fmaxf(m, __shfl_xor_sync(0xffffffff, m, off));
    float ssum = 0.f;
    for (int i = 0; i < cnt; i++) { vals[i] = __expf(vals[i] - m); ssum += vals[i]; }
    for (int off = 16; off > 0; off >>= 1)
        ssum += __shfl_xor_sync(0xffffffff, ssum, off);
    float inv = 1.0f / ssum;
    int c2 = 0;
    for (int kk = lane; kk < SEQ; kk += 32) {
        if (kk < n) p[kk] = vals[c2++] * inv;
        else        p[kk] = 0.f;
    }
}

// ---------------- PV: attn @ V -> g_att (interleaved head layout) ----------------
__global__ void pv_kernel(const float* __restrict__ v) {
    int qt = blockIdx.x;           // 0..14, 16 query rows each
    int bh = blockIdx.y;
    int b = bh / NHEAD, h = bh % NHEAD;
    __shared__ float As[16][16];
    __shared__ float Vs[16][64];
    int tid = threadIdx.x;
    int tx = tid & 63;            // d
    int tg = tid >> 6;            // 0..3
    int q0 = qt * 16;
    float acc[4] = {0.f, 0.f, 0.f, 0.f};
    int kmax = q0 + 16;
    for (int k0 = 0; k0 < kmax; k0 += 16) {
        {   // load As 16x16 (one float each) and Vs 16x64 (float4 each)
            int r = tid >> 4, c = tid & 15;
            As[r][c] = g_sc[((long long)bh * SEQ + q0 + r) * SEQ + k0 + c];
            int vr = tid >> 4, vc = (tid & 15) * 4;
            *(float4*)&Vs[vr][vc] =
                *(const float4*)&v[((long long)(b*SEQ + k0 + vr) * HID) + h*DHEAD + vc];
        }
        __syncthreads();
#pragma unroll
        for (int kk = 0; kk < 16; kk++) {
            float vv = Vs[kk][tx];
#pragma unroll
            for (int i = 0; i < 4; i++)
                acc[i] += As[tg*4+i][kk] * vv;
        }
        __syncthreads();
    }
#pragma unroll
    for (int i = 0; i < 4; i++)
        g_att[((long long)(b*SEQ + q0 + tg*4 + i) * HID) + h*DHEAD + tx] = acc[i];
}

// ---------------- residual add + LayerNorm ----------------
__global__ void add_ln_kernel(const float* __restrict__ a, const float* __restrict__ r,
                              const float* __restrict__ sc, const float* __restrict__ bi,
                              float* __restrict__ out) {
    int row = blockIdx.x;
    int tid = threadIdx.x;
    const float* ap = a + (long long)row * HID;
    const float* rp = r + (long long)row * HID;
    float v[4];
    float s = 0.f, sq = 0.f;
#pragma unroll
    for (int j = 0; j < 4; j++) {
        int h = tid + j*256;
        v[j] = ap[h] + rp[h];
        s  += v[j];
        sq += v[j]*v[j];
    }
    __shared__ float red1[8], red2[8];
    for (int off = 16; off > 0; off >>= 1) {
        s  += __shfl_xor_sync(0xffffffff, s,  off);
        sq += __shfl_xor_sync(0xffffffff, sq, off);
    }
    int warp = tid >> 5, lane = tid & 31;
    if (lane == 0) { red1[warp] = s; red2[warp] = sq; }
    __syncthreads();
    if (warp == 0) {
        s  = (lane < 8) ? red1[lane] : 0.f;
        sq = (lane < 8) ? red2[lane] : 0.f;
        for (int off = 4; off > 0; off >>= 1) {
            s  += __shfl_xor_sync(0xffffffff, s,  off);
            sq += __shfl_xor_sync(0xffffffff, sq, off);
        }
        if (lane == 0) { red1[0] = s; red2[0] = sq; }
    }
    __syncthreads();
    float mean = red1[0] * (1.0f / HID);
    float var  = red2[0] * (1.0f / HID) - mean * mean;
    float rstd = rsqrtf(var + 1e-5f);
    float* op = out + (long long)row * HID;
#pragma unroll
    for (int j = 0; j < 4; j++) {
        int h = tid + j*256;
        op[h] = (v[j] - mean) * rstd * sc[h] + bi[h];
    }
}

// ---------------- mean-pool over S (includes padded positions, faithful) ----------------
__global__ void pool_kernel() {
    int b = blockIdx.y;
    int h = blockIdx.x * 256 + threadIdx.x;
    float s = 0.f;
    const float* zp = g_z + (long long)b * SEQ * HID + h;
    for (int si = 0; si < SEQ; si++)
        s += zp[(long long)si * HID];
    g_pool[b * HID + h] = s * (1.0f / SEQ);
}

// ---------------- classifier head + softmax(4) ----------------
__global__ void head_kernel(const float* __restrict__ Wfc, const float* __restrict__ bfc,
                            float* __restrict__ out) {
    int b = blockIdx.x;
    int tid = threadIdx.x;
    float p[4] = {0.f, 0.f, 0.f, 0.f};
    const float* zp = g_pool + b * HID;
    for (int h = tid; h < HID; h += 256) {
        float zv = zp[h];
#pragma unroll
        for (int c = 0; c < 4; c++) p[c] += zv * Wfc[h*4 + c];
    }
    __shared__ float red[4][256];
#pragma unroll
    for (int c = 0; c < 4; c++) red[c][tid] = p[c];
    __syncthreads();
    for (int str = 128; str > 0; str >>= 1) {
        if (tid < str)
#pragma unroll
            for (int c = 0; c < 4; c++) red[c][tid] += red[c][tid + str];
        __syncthreads();
    }
    if (tid == 0) {
        float l[4];
        float m = -1e30f;
#pragma unroll
        for (int c = 0; c < 4; c++) { l[c] = red[c][0] + bfc[c]; m = fmaxf(m, l[c]); }
        float ssum = 0.f;
#pragma unroll
        for (int c = 0; c < 4; c++) { l[c] = __expf(l[c] - m); ssum += l[c]; }
        float inv = 1.0f / ssum;
#pragma unroll
        for (int c = 0; c < 4; c++) out[b*4 + c] = l[c] * inv;
    }
}

// ---------------- host orchestration ----------------
extern "C" void kernel_launch(void* const* d_in, const int* in_sizes, int n_in,
                              void* d_out, int out_size) {
    const float* x     = (const float*)d_in[0];
    const float* w_emb = (const float*)d_in[1];
    const float* p_emb = (const float*)d_in[2];
    const float* Wq    = (const float*)d_in[3];
    const float* bq    = (const float*)d_in[4];
    const float* Wk    = (const float*)d_in[5];
    const float* bk    = (const float*)d_in[6];
    const float* Wv    = (const float*)d_in[7];
    const float* bv    = (const float*)d_in[8];
    const float* W1    = (const float*)d_in[9];
    const float* b1    = (const float*)d_in[10];
    const float* W2    = (const float*)d_in[11];
    const float* b2    = (const float*)d_in[12];
    const float* ln1_s = (const float*)d_in[13];
    const float* ln1_b = (const float*)d_in[14];
    const float* ln2_s = (const float*)d_in[15];
    const float* ln2_b = (const float*)d_in[16];
    const float* Wfc   = (const float*)d_in[17];
    const float* bfc   = (const float*)d_in[18];
    const int*   lengths = (const int*)d_in[19];
    float* out = (float*)d_out;

    float *pz, *pq, *pk, *pv, *patt, *pz1, *pffh;
    cudaGetSymbolAddress((void**)&pz,   g_z);
    cudaGetSymbolAddress((void**)&pq,   g_q);
    cudaGetSymbolAddress((void**)&pk,   g_k);
    cudaGetSymbolAddress((void**)&pv,   g_v);
    cudaGetSymbolAddress((void**)&patt, g_att);
    cudaGetSymbolAddress((void**)&pz1,  g_z1);
    cudaGetSymbolAddress((void**)&pffh, g_ffh);

    embed_kernel<<<BS_TOT, 256>>>(x, w_emb, p_emb, lengths);

    dim3 gemm_grid(HID/128, BS_TOT/128);   // (8, 60)
    dim3 sc_grid(SEQ/16, SEQ/16, NB*NHEAD); // (15,15,512)
    dim3 pv_grid(SEQ/16, NB*NHEAD);

    for (int i = 0; i < NLAYER; i++) {
        long long wOff = (long long)i * HID * HID;
        long long bOff = (long long)i * HID;
        sgemm_bias<0><<<gemm_grid, 256>>>(pz, Wq + wOff, bq + bOff, pq);
        sgemm_bias<0><<<gemm_grid, 256>>>(pz, Wk + wOff, bk + bOff, pk);
        sgemm_bias<0><<<gemm_grid, 256>>>(pz, Wv + wOff, bv + bOff, pv);
        scores_kernel<<<sc_grid, 256>>>(pq, pk);
        softmax_kernel<<<NB*NHEAD*SEQ/8, 256>>>(lengths);
        pv_kernel<<<pv_grid, 256>>>(pv);
        add_ln_kernel<<<BS_TOT, 256>>>(pz, patt, ln1_s + bOff, ln1_b + bOff, pz1);
        sgemm_bias<1><<<gemm_grid, 256>>>(pz1, W1 + wOff, b1 + bOff, pffh);
        sgemm_bias<0><<<gemm_grid, 256>>>(pffh, W2 + wOff, b2 + bOff, patt);
        add_ln_kernel<<<BS_TOT, 256>>>(pz1, patt, ln2_s + bOff, ln2_b + bOff, pz);
    }

    pool_kernel<<<dim3(HID/256, NB), 256>>>();
    head_kernel<<<NB, 256>>>(Wfc, bfc, out);
}

// round 6
// speedup vs baseline: 2.2760x; 2.2760x over previous
#include <cuda_runtime.h>
#include <math.h>
#include <cstdint>

#define NB     32
#define SEQ    240
#define HID    1024
#define NLAYER 8
#define NHEAD  16
#define DHEAD  64
#define NVOCAB 48
#define BS_TOT (NB*SEQ)   // 7680

// ---------------- device scratch (no allocation allowed) ----------------
__device__ float g_z  [BS_TOT*HID];
__device__ float g_q  [BS_TOT*HID];
__device__ float g_k  [BS_TOT*HID];
__device__ float g_v  [BS_TOT*HID];
__device__ float g_att[BS_TOT*HID];
__device__ float g_z1 [BS_TOT*HID];
__device__ float g_ffh[BS_TOT*HID];
__device__ float g_sc [NB*NHEAD*SEQ*SEQ];          // 118 MB scores/probs
__device__ float g_pool[NB*HID];
__device__ float g_wt [5ll*NLAYER*HID*HID];        // 160 MB transposed weights [N,K]

// ============================ helpers ============================
__device__ __forceinline__ uint32_t smem_u32(const void* p) {
    return (uint32_t)__cvta_generic_to_shared(p);
}
__device__ __forceinline__ void cpa16(uint32_t dst, const void* src) {
    asm volatile("cp.async.cg.shared.global [%0], [%1], 16;" :: "r"(dst), "l"(src));
}
#define CPA_COMMIT() asm volatile("cp.async.commit_group;" ::: "memory")
template<int N> __device__ __forceinline__ void cpa_wait() {
    asm volatile("cp.async.wait_group %0;" :: "n"(N) : "memory");
}

__device__ __forceinline__ void mma_tf32(float* c, const uint32_t* a, uint32_t b0, uint32_t b1) {
    asm volatile(
        "mma.sync.aligned.m16n8k8.row.col.f32.tf32.tf32.f32 "
        "{%0,%1,%2,%3}, {%4,%5,%6,%7}, {%8,%9}, {%0,%1,%2,%3};"
        : "+f"(c[0]), "+f"(c[1]), "+f"(c[2]), "+f"(c[3])
        : "r"(a[0]), "r"(a[1]), "r"(a[2]), "r"(a[3]), "r"(b0), "r"(b1));
}

// ============================ weight transpose ============================
// dst[n*HID + k] = src[k*HID + n], one [HID,HID] matrix per blockIdx.z
__global__ void transpose_kernel(const float* __restrict__ src, float* __restrict__ dst) {
    __shared__ float t[32][33];
    long long moff = (long long)blockIdx.z * HID * HID;
    int x0 = blockIdx.x * 32, y0 = blockIdx.y * 32;
    int tx = threadIdx.x, ty = threadIdx.y;  // 32 x 8
#pragma unroll
    for (int j = 0; j < 32; j += 8)
        t[ty + j][tx] = src[moff + (long long)(y0 + ty + j) * HID + x0 + tx];
    __syncthreads();
#pragma unroll
    for (int j = 0; j < 32; j += 8)
        dst[moff + (long long)(x0 + ty + j) * HID + y0 + tx] = t[tx][ty + j];
}

// ============================ tf32 mma.sync GEMM ============================
// C[M,N] = A[M,K] @ Wt^T + bias ; A row-major [M,K], Wt row-major [N,K].
// BM=128, BN=128, BK=16; 256 threads; warp grid 4x2, warp tile 32x64.
#define BKC   16
#define PADK  20                       // padded smem row stride (floats)
#define ABYTES (128 * PADK * 4)        // 10240
#define STAGEB (2 * ABYTES)            // 20480 (A+B)
#define NSTAGE 3
#define GEMM_SMEM (NSTAGE * STAGEB)    // 61440

__device__ __forceinline__ void gemm_load_stage(uint32_t sbase, int s, int kc, int tid,
                                                const float* __restrict__ A,
                                                const float* __restrict__ Bw,
                                                int row0, int col0) {
    uint32_t abase = sbase + s * STAGEB;
    uint32_t bbase = abase + ABYTES;
    const float* Ag = A  + (long long)row0 * HID + kc * BKC;
    const float* Bg = Bw + (long long)col0 * HID + kc * BKC;
#pragma unroll
    for (int j = 0; j < 2; j++) {
        int c = tid + j * 256;          // 0..511
        int r = c >> 2, q = c & 3;      // row 0..127, 16B-chunk 0..3
        uint32_t so = (uint32_t)(r * PADK + q * 4) * 4;
        cpa16(abase + so, Ag + (long long)r * HID + q * 4);
        cpa16(bbase + so, Bg + (long long)r * HID + q * 4);
    }
}

template<int ACT>
__global__ __launch_bounds__(256)
void gemm_tc(const float* __restrict__ A, const float* __restrict__ Bw,
             const float* __restrict__ bias, float* __restrict__ C) {
    extern __shared__ float smem[];
    const int tid = threadIdx.x;
    const int wid = tid >> 5, lane = tid & 31;
    const int wm = wid & 3, wn = wid >> 2;
    const int grp = lane >> 2, qid = lane & 3;
    const int row0 = blockIdx.y * 128;
    const int col0 = blockIdx.x * 128;
    uint32_t sbase = smem_u32(smem);

    float acc[2][8][4];
#pragma unroll
    for (int mf = 0; mf < 2; mf++)
#pragma unroll
        for (int nf = 0; nf < 8; nf++)
#pragma unroll
            for (int i = 0; i < 4; i++) acc[mf][nf][i] = 0.f;

    const int NKC = HID / BKC;   // 64

    gemm_load_stage(sbase, 0, 0, tid, A, Bw, row0, col0);
    CPA_COMMIT();
    gemm_load_stage(sbase, 1, 1, tid, A, Bw, row0, col0);
    CPA_COMMIT();

    for (int kc = 0; kc < NKC; kc++) {
        int s = kc % NSTAGE;
        if (kc + 2 < NKC)
            gemm_load_stage(sbase, (kc + 2) % NSTAGE, kc + 2, tid, A, Bw, row0, col0);
        CPA_COMMIT();
        cpa_wait<2>();
        __syncthreads();

        const float* sA = smem + s * (STAGEB / 4);
        const float* sB = sA + (ABYTES / 4);
#pragma unroll
        for (int kk = 0; kk < 2; kk++) {
            int k8 = kk * 8;
            uint32_t af[2][4];
#pragma unroll
            for (int mf = 0; mf < 2; mf++) {
                const float* p = sA + (wm * 32 + mf * 16 + grp) * PADK + k8 + qid;
                af[mf][0] = __float_as_uint(p[0]);
                af[mf][1] = __float_as_uint(p[8 * PADK]);
                af[mf][2] = __float_as_uint(p[4]);
                af[mf][3] = __float_as_uint(p[8 * PADK + 4]);
            }
#pragma unroll
            for (int nf = 0; nf < 8; nf++) {
                const float* p = sB + (wn * 64 + nf * 8 + grp) * PADK + k8 + qid;
                uint32_t b0 = __float_as_uint(p[0]);
                uint32_t b1 = __float_as_uint(p[4]);
                mma_tf32(acc[0][nf], af[0], b0, b1);
                mma_tf32(acc[1][nf], af[1], b0, b1);
            }
        }
        __syncthreads();
    }

    // epilogue
#pragma unroll
    for (int mf = 0; mf < 2; mf++) {
        int r0 = row0 + wm * 32 + mf * 16 + grp;
#pragma unroll
        for (int nf = 0; nf < 8; nf++) {
            int cg = col0 + wn * 64 + nf * 8 + 2 * qid;
            float bv0 = bias[cg], bv1 = bias[cg + 1];
            float v00 = acc[mf][nf][0] + bv0;
            float v01 = acc[mf][nf][1] + bv1;
            float v10 = acc[mf][nf][2] + bv0;
            float v11 = acc[mf][nf][3] + bv1;
            if (ACT) {
                v00 = 0.5f * v00 * (1.0f + erff(v00 * 0.70710678118654752f));
                v01 = 0.5f * v01 * (1.0f + erff(v01 * 0.70710678118654752f));
                v10 = 0.5f * v10 * (1.0f + erff(v10 * 0.70710678118654752f));
                v11 = 0.5f * v11 * (1.0f + erff(v11 * 0.70710678118654752f));
            }
            *(float2*)&C[(long long)r0 * HID + cg]       = make_float2(v00, v01);
            *(float2*)&C[(long long)(r0 + 8) * HID + cg] = make_float2(v10, v11);
        }
    }
}

// ---------------- embedding: argmax + gather + posenc ----------------
__global__ void embed_kernel(const float* __restrict__ x,
                             const float* __restrict__ w_emb,
                             const float* __restrict__ p_emb,
                             const int*   __restrict__ lengths) {
    int bs = blockIdx.x;
    int b = bs / SEQ, s = bs % SEQ;
    __shared__ int s_tok;
    int tid = threadIdx.x;
    if (tid < 32) {
        const float* xp = x + (long long)bs * NVOCAB;
        float bv = -1e30f; int bi = 0;
        for (int c = tid; c < NVOCAB; c += 32) {
            float v = xp[c];
            if (v > bv) { bv = v; bi = c; }
        }
        for (int off = 16; off > 0; off >>= 1) {
            float ov = __shfl_down_sync(0xffffffff, bv, off);
            int   oi = __shfl_down_sync(0xffffffff, bi, off);
            if (ov > bv || (ov == bv && oi < bi)) { bv = ov; bi = oi; }
        }
        if (tid == 0) s_tok = bi;
    }
    __syncthreads();
    int tok = s_tok;
    float valid = (s < lengths[b]) ? 1.0f : 0.0f;
    const float* we = w_emb + (long long)tok * HID;
    const float* pe = p_emb + (long long)s * HID;
    float* zp = g_z + (long long)bs * HID;
    for (int h = tid; h < HID; h += blockDim.x)
        zp[h] = we[h] * valid + pe[h];
}

// ---------------- attention scores: Q @ K^T * scale, causal tiles only ----------------
__global__ void scores_kernel(const float* __restrict__ q, const float* __restrict__ k) {
    int kt = blockIdx.x, qt = blockIdx.y;
    if (kt > qt) return;
    int bh = blockIdx.z;
    int b = bh / NHEAD, h = bh % NHEAD;
    __shared__ float Qs[16][68];
    __shared__ float Ks[16][68];
    int tid = threadIdx.x;
    {
        int row = tid >> 4, c4 = (tid & 15) * 4;
        const float* qg = q + ((long long)(b*SEQ + qt*16 + row) * HID) + h*DHEAD + c4;
        const float* kg = k + ((long long)(b*SEQ + kt*16 + row) * HID) + h*DHEAD + c4;
        *(float4*)&Qs[row][c4] = *(const float4*)qg;
        *(float4*)&Ks[row][c4] = *(const float4*)kg;
    }
    __syncthreads();
    int ty = tid >> 4, tx = tid & 15;
    float acc = 0.f;
#pragma unroll
    for (int d4 = 0; d4 < 16; d4++) {
        float4 qa = *(const float4*)&Qs[ty][d4*4];
        float4 ka = *(const float4*)&Ks[tx][d4*4];
        acc += qa.x*ka.x + qa.y*ka.y + qa.z*ka.z + qa.w*ka.w;
    }
    int qg = qt*16 + ty, kg = kt*16 + tx;
    float out = (kg <= qg) ? acc * (1.0f/32.0f) : 0.0f;
    g_sc[((long long)bh * SEQ + qg) * SEQ + kg] = out;
}

// ---------------- softmax per row ----------------
__global__ void softmax_kernel(const int* __restrict__ lengths) {
    int warp = threadIdx.x >> 5;
    int lane = threadIdx.x & 31;
    long long row = (long long)blockIdx.x * 8 + warp;
    int bh = (int)(row / SEQ);
    int qi = (int)(row % SEQ);
    int b = bh / NHEAD;
    float* p = g_sc + row * SEQ;
    int len = lengths[b];
    if (qi >= len) {
        for (int kk = lane; kk < SEQ; kk += 32) p[kk] = 0.f;
        return;
    }
    int n = qi + 1;
    float vals[8];
    int cnt = 0;
    float m = -1e30f;
    for (int kk = lane; kk < n; kk += 32) {
        vals[cnt] = p[kk];
        m = fmaxf(m, vals[cnt]);
        cnt++;
    }
    for (int off = 16; off > 0; off >>= 1)
        m = fmaxf(m, __shfl_xor_sync(0xffffffff, m, off));
    float ssum = 0.f;
    for (int i = 0; i < cnt; i++) { vals[i] = __expf(vals[i] - m); ssum += vals[i]; }
    for (int off = 16; off > 0; off >>= 1)
        ssum += __shfl_xor_sync(0xffffffff, ssum, off);
    float inv = 1.0f / ssum;
    int c2 = 0;
    for (int kk = lane; kk < SEQ; kk += 32) {
        if (kk < n) p[kk] = vals[c2++] * inv;
        else        p[kk] = 0.f;
    }
}

// ---------------- PV: attn @ V -> g_att ----------------
__global__ void pv_kernel(const float* __restrict__ v) {
    int qt = blockIdx.x;
    int bh = blockIdx.y;
    int b = bh / NHEAD, h = bh % NHEAD;
    __shared__ float As[16][16];
    __shared__ float Vs[16][64];
    int tid = threadIdx.x;
    int tx = tid & 63;
    int tg = tid >> 6;
    int q0 = qt * 16;
    float acc[4] = {0.f, 0.f, 0.f, 0.f};
    int kmax = q0 + 16;
    for (int k0 = 0; k0 < kmax; k0 += 16) {
        {
            int r = tid >> 4, c = tid & 15;
            As[r][c] = g_sc[((long long)bh * SEQ + q0 + r) * SEQ + k0 + c];
            int vr = tid >> 4, vc = (tid & 15) * 4;
            *(float4*)&Vs[vr][vc] =
                *(const float4*)&v[((long long)(b*SEQ + k0 + vr) * HID) + h*DHEAD + vc];
        }
        __syncthreads();
#pragma unroll
        for (int kk = 0; kk < 16; kk++) {
            float vv = Vs[kk][tx];
#pragma unroll
            for (int i = 0; i < 4; i++)
                acc[i] += As[tg*4+i][kk] * vv;
        }
        __syncthreads();
    }
#pragma unroll
    for (int i = 0; i < 4; i++)
        g_att[((long long)(b*SEQ + q0 + tg*4 + i) * HID) + h*DHEAD + tx] = acc[i];
}

// ---------------- residual add + LayerNorm ----------------
__global__ void add_ln_kernel(const float* __restrict__ a, const float* __restrict__ r,
                              const float* __restrict__ sc, const float* __restrict__ bi,
                              float* __restrict__ out) {
    int row = blockIdx.x;
    int tid = threadIdx.x;
    const float* ap = a + (long long)row * HID;
    const float* rp = r + (long long)row * HID;
    float v[4];
    float s = 0.f, sq = 0.f;
#pragma unroll
    for (int j = 0; j < 4; j++) {
        int h = tid + j*256;
        v[j] = ap[h] + rp[h];
        s  += v[j];
        sq += v[j]*v[j];
    }
    __shared__ float red1[8], red2[8];
    for (int off = 16; off > 0; off >>= 1) {
        s  += __shfl_xor_sync(0xffffffff, s,  off);
        sq += __shfl_xor_sync(0xffffffff, sq, off);
    }
    int warp = tid >> 5, lane = tid & 31;
    if (lane == 0) { red1[warp] = s; red2[warp] = sq; }
    __syncthreads();
    if (warp == 0) {
        s  = (lane < 8) ? red1[lane] : 0.f;
        sq = (lane < 8) ? red2[lane] : 0.f;
        for (int off = 4; off > 0; off >>= 1) {
            s  += __shfl_xor_sync(0xffffffff, s,  off);
            sq += __shfl_xor_sync(0xffffffff, sq, off);
        }
        if (lane == 0) { red1[0] = s; red2[0] = sq; }
    }
    __syncthreads();
    float mean = red1[0] * (1.0f / HID);
    float var  = red2[0] * (1.0f / HID) - mean * mean;
    float rstd = rsqrtf(var + 1e-5f);
    float* op = out + (long long)row * HID;
#pragma unroll
    for (int j = 0; j < 4; j++) {
        int h = tid + j*256;
        op[h] = (v[j] - mean) * rstd * sc[h] + bi[h];
    }
}

// ---------------- mean-pool ----------------
__global__ void pool_kernel() {
    int b = blockIdx.y;
    int h = blockIdx.x * 256 + threadIdx.x;
    float s = 0.f;
    const float* zp = g_z + (long long)b * SEQ * HID + h;
    for (int si = 0; si < SEQ; si++)
        s += zp[(long long)si * HID];
    g_pool[b * HID + h] = s * (1.0f / SEQ);
}

// ---------------- classifier head + softmax(4) ----------------
__global__ void head_kernel(const float* __restrict__ Wfc, const float* __restrict__ bfc,
                            float* __restrict__ out) {
    int b = blockIdx.x;
    int tid = threadIdx.x;
    float p[4] = {0.f, 0.f, 0.f, 0.f};
    const float* zp = g_pool + b * HID;
    for (int h = tid; h < HID; h += 256) {
        float zv = zp[h];
#pragma unroll
        for (int c = 0; c < 4; c++) p[c] += zv * Wfc[h*4 + c];
    }
    __shared__ float red[4][256];
#pragma unroll
    for (int c = 0; c < 4; c++) red[c][tid] = p[c];
    __syncthreads();
    for (int str = 128; str > 0; str >>= 1) {
        if (tid < str)
#pragma unroll
            for (int c = 0; c < 4; c++) red[c][tid] += red[c][tid + str];
        __syncthreads();
    }
    if (tid == 0) {
        float l[4];
        float m = -1e30f;
#pragma unroll
        for (int c = 0; c < 4; c++) { l[c] = red[c][0] + bfc[c]; m = fmaxf(m, l[c]); }
        float ssum = 0.f;
#pragma unroll
        for (int c = 0; c < 4; c++) { l[c] = __expf(l[c] - m); ssum += l[c]; }
        float inv = 1.0f / ssum;
#pragma unroll
        for (int c = 0; c < 4; c++) out[b*4 + c] = l[c] * inv;
    }
}

// ---------------- host orchestration ----------------
extern "C" void kernel_launch(void* const* d_in, const int* in_sizes, int n_in,
                              void* d_out, int out_size) {
    const float* x     = (const float*)d_in[0];
    const float* w_emb = (const float*)d_in[1];
    const float* p_emb = (const float*)d_in[2];
    const float* Wq    = (const float*)d_in[3];
    const float* bq    = (const float*)d_in[4];
    const float* Wk    = (const float*)d_in[5];
    const float* bk    = (const float*)d_in[6];
    const float* Wv    = (const float*)d_in[7];
    const float* bv    = (const float*)d_in[8];
    const float* W1    = (const float*)d_in[9];
    const float* b1    = (const float*)d_in[10];
    const float* W2    = (const float*)d_in[11];
    const float* b2    = (const float*)d_in[12];
    const float* ln1_s = (const float*)d_in[13];
    const float* ln1_b = (const float*)d_in[14];
    const float* ln2_s = (const float*)d_in[15];
    const float* ln2_b = (const float*)d_in[16];
    const float* Wfc   = (const float*)d_in[17];
    const float* bfc   = (const float*)d_in[18];
    const int*   lengths = (const int*)d_in[19];
    float* out = (float*)d_out;

    float *pz, *pq, *pk, *pv, *patt, *pz1, *pffh, *pwt;
    cudaGetSymbolAddress((void**)&pz,   g_z);
    cudaGetSymbolAddress((void**)&pq,   g_q);
    cudaGetSymbolAddress((void**)&pk,   g_k);
    cudaGetSymbolAddress((void**)&pv,   g_v);
    cudaGetSymbolAddress((void**)&patt, g_att);
    cudaGetSymbolAddress((void**)&pz1,  g_z1);
    cudaGetSymbolAddress((void**)&pffh, g_ffh);
    cudaGetSymbolAddress((void**)&pwt,  g_wt);

    cudaFuncSetAttribute(gemm_tc<0>, cudaFuncAttributeMaxDynamicSharedMemorySize, GEMM_SMEM);
    cudaFuncSetAttribute(gemm_tc<1>, cudaFuncAttributeMaxDynamicSharedMemorySize, GEMM_SMEM);

    const long long MAT  = (long long)HID * HID;
    const long long TYPE = (long long)NLAYER * MAT;

    // transpose all weights to [N,K] K-major layout
    dim3 tgrid(HID/32, HID/32, NLAYER);
    dim3 tblk(32, 8);
    transpose_kernel<<<tgrid, tblk>>>(Wq, pwt + 0*TYPE);
    transpose_kernel<<<tgrid, tblk>>>(Wk, pwt + 1*TYPE);
    transpose_kernel<<<tgrid, tblk>>>(Wv, pwt + 2*TYPE);
    transpose_kernel<<<tgrid, tblk>>>(W1, pwt + 3*TYPE);
    transpose_kernel<<<tgrid, tblk>>>(W2, pwt + 4*TYPE);

    embed_kernel<<<BS_TOT, 256>>>(x, w_emb, p_emb, lengths);

    dim3 gemm_grid(HID/128, BS_TOT/128);      // (8, 60)
    dim3 sc_grid(SEQ/16, SEQ/16, NB*NHEAD);
    dim3 pv_grid(SEQ/16, NB*NHEAD);

    for (int i = 0; i < NLAYER; i++) {
        long long wOff = (long long)i * MAT;
        long long bOff = (long long)i * HID;
        gemm_tc<0><<<gemm_grid, 256, GEMM_SMEM>>>(pz, pwt + 0*TYPE + wOff, bq + bOff, pq);
        gemm_tc<0><<<gemm_grid, 256, GEMM_SMEM>>>(pz, pwt + 1*TYPE + wOff, bk + bOff, pk);
        gemm_tc<0><<<gemm_grid, 256, GEMM_SMEM>>>(pz, pwt + 2*TYPE + wOff, bv + bOff, pv);
        scores_kernel<<<sc_grid, 256>>>(pq, pk);
        softmax_kernel<<<NB*NHEAD*SEQ/8, 256>>>(lengths);
        pv_kernel<<<pv_grid, 256>>>(pv);
        add_ln_kernel<<<BS_TOT, 256>>>(pz, patt, ln1_s + bOff, ln1_b + bOff, pz1);
        gemm_tc<1><<<gemm_grid, 256, GEMM_SMEM>>>(pz1, pwt + 3*TYPE + wOff, b1 + bOff, pffh);
        gemm_tc<0><<<gemm_grid, 256, GEMM_SMEM>>>(pffh, pwt + 4*TYPE + wOff, b2 + bOff, patt);
        add_ln_kernel<<<BS_TOT, 256>>>(pz1, patt, ln2_s + bOff, ln2_b + bOff, pz);
    }

    pool_kernel<<<dim3(HID/256, NB), 256>>>();
    head_kernel<<<NB, 256>>>(Wfc, bfc, out);
}

// round 7
// speedup vs baseline: 2.9713x; 1.3055x over previous
#include <cuda_runtime.h>
#include <math.h>
#include <cstdint>

#define NB     32
#define SEQ    240
#define HID    1024
#define NLAYER 8
#define NHEAD  16
#define DHEAD  64
#define NVOCAB 48
#define BS_TOT (NB*SEQ)   // 7680
#define QKVW   3072

// ---------------- device scratch (no allocation allowed) ----------------
__device__ float g_z   [BS_TOT*HID];
__device__ float g_qkv [(long long)BS_TOT*QKVW];   // packed Q|K|V per row
__device__ float g_att [BS_TOT*HID];
__device__ float g_z1  [BS_TOT*HID];
__device__ float g_ffh [BS_TOT*HID];
__device__ float g_pool[NB*HID];
__device__ float g_wqkv[(long long)NLAYER*3*HID*HID];  // [L][3072][1024] transposed
__device__ float g_w12 [(long long)NLAYER*2*HID*HID];  // [L][W1t|W2t]
__device__ float g_bqkv[NLAYER*QKVW];

// ============================ helpers ============================
__device__ __forceinline__ uint32_t smem_u32(const void* p) {
    return (uint32_t)__cvta_generic_to_shared(p);
}
__device__ __forceinline__ void cpa16(uint32_t dst, const void* src) {
    asm volatile("cp.async.cg.shared.global [%0], [%1], 16;" :: "r"(dst), "l"(src));
}
#define CPA_COMMIT() asm volatile("cp.async.commit_group;" ::: "memory")
template<int N> __device__ __forceinline__ void cpa_wait() {
    asm volatile("cp.async.wait_group %0;" :: "n"(N) : "memory");
}

__device__ __forceinline__ void mma_tf32(float* c, const uint32_t* a, uint32_t b0, uint32_t b1) {
    asm volatile(
        "mma.sync.aligned.m16n8k8.row.col.f32.tf32.tf32.f32 "
        "{%0,%1,%2,%3}, {%4,%5,%6,%7}, {%8,%9}, {%0,%1,%2,%3};"
        : "+f"(c[0]), "+f"(c[1]), "+f"(c[2]), "+f"(c[3])
        : "r"(a[0]), "r"(a[1]), "r"(a[2]), "r"(a[3]), "r"(b0), "r"(b1));
}

// ============================ weight transpose ============================
// dst[n*HID + k] = src[k*HID + n]; src z-stride = HID*HID, dst z-stride = dstZ.
__global__ void transpose_kernel(const float* __restrict__ src, float* __restrict__ dst,
                                 long long dstZ) {
    __shared__ float t[32][33];
    long long smoff = (long long)blockIdx.z * HID * HID;
    long long dmoff = (long long)blockIdx.z * dstZ;
    int x0 = blockIdx.x * 32, y0 = blockIdx.y * 32;
    int tx = threadIdx.x, ty = threadIdx.y;  // 32 x 8
#pragma unroll
    for (int j = 0; j < 32; j += 8)
        t[ty + j][tx] = src[smoff + (long long)(y0 + ty + j) * HID + x0 + tx];
    __syncthreads();
#pragma unroll
    for (int j = 0; j < 32; j += 8)
        dst[dmoff + (long long)(x0 + ty + j) * HID + y0 + tx] = t[tx][ty + j];
}

// bias pack: g_bqkv[l][t*1024+n]
__global__ void biaspack_kernel(const float* __restrict__ bq, const float* __restrict__ bk,
                                const float* __restrict__ bv) {
    int idx = blockIdx.x * 256 + threadIdx.x;
    if (idx >= NLAYER * QKVW) return;
    int l = idx / QKVW, r = idx % QKVW;
    int t = r >> 10, n = r & 1023;
    const float* src = (t == 0) ? bq : (t == 1) ? bk : bv;
    g_bqkv[idx] = src[l * HID + n];
}

// ============================ tf32 mma.sync GEMM ============================
// C[M,N] = A[M,K] @ Wt^T + bias ; A row-major [M,K] (lda=HID), Wt row-major [N,K].
#define BKC   16
#define PADK  20
#define ABYTES (128 * PADK * 4)
#define STAGEB (2 * ABYTES)
#define NSTAGE 3
#define GEMM_SMEM (NSTAGE * STAGEB)

__device__ __forceinline__ void gemm_load_stage(uint32_t sbase, int s, int kc, int tid,
                                                const float* __restrict__ A,
                                                const float* __restrict__ Bw,
                                                int row0, int col0) {
    uint32_t abase = sbase + s * STAGEB;
    uint32_t bbase = abase + ABYTES;
    const float* Ag = A  + (long long)row0 * HID + kc * BKC;
    const float* Bg = Bw + (long long)col0 * HID + kc * BKC;
#pragma unroll
    for (int j = 0; j < 2; j++) {
        int c = tid + j * 256;
        int r = c >> 2, q = c & 3;
        uint32_t so = (uint32_t)(r * PADK + q * 4) * 4;
        cpa16(abase + so, Ag + (long long)r * HID + q * 4);
        cpa16(bbase + so, Bg + (long long)r * HID + q * 4);
    }
}

template<int ACT>
__global__ __launch_bounds__(256, 2)
void gemm_tc(const float* __restrict__ A, const float* __restrict__ Bw,
             const float* __restrict__ bias, float* __restrict__ C, int ldC) {
    extern __shared__ float smem[];
    const int tid = threadIdx.x;
    const int wid = tid >> 5, lane = tid & 31;
    const int wm = wid & 3, wn = wid >> 2;
    const int grp = lane >> 2, qid = lane & 3;
    const int row0 = blockIdx.y * 128;
    const int col0 = blockIdx.x * 128;
    uint32_t sbase = smem_u32(smem);

    float acc[2][8][4];
#pragma unroll
    for (int mf = 0; mf < 2; mf++)
#pragma unroll
        for (int nf = 0; nf < 8; nf++)
#pragma unroll
            for (int i = 0; i < 4; i++) acc[mf][nf][i] = 0.f;

    const int NKC = HID / BKC;

    gemm_load_stage(sbase, 0, 0, tid, A, Bw, row0, col0);
    CPA_COMMIT();
    gemm_load_stage(sbase, 1, 1, tid, A, Bw, row0, col0);
    CPA_COMMIT();

    for (int kc = 0; kc < NKC; kc++) {
        int s = kc % NSTAGE;
        if (kc + 2 < NKC)
            gemm_load_stage(sbase, (kc + 2) % NSTAGE, kc + 2, tid, A, Bw, row0, col0);
        CPA_COMMIT();
        cpa_wait<2>();
        __syncthreads();

        const float* sA = smem + s * (STAGEB / 4);
        const float* sB = sA + (ABYTES / 4);
#pragma unroll
        for (int kk = 0; kk < 2; kk++) {
            int k8 = kk * 8;
            uint32_t af[2][4];
#pragma unroll
            for (int mf = 0; mf < 2; mf++) {
                const float* p = sA + (wm * 32 + mf * 16 + grp) * PADK + k8 + qid;
                af[mf][0] = __float_as_uint(p[0]);
                af[mf][1] = __float_as_uint(p[8 * PADK]);
                af[mf][2] = __float_as_uint(p[4]);
                af[mf][3] = __float_as_uint(p[8 * PADK + 4]);
            }
#pragma unroll
            for (int nf = 0; nf < 8; nf++) {
                const float* p = sB + (wn * 64 + nf * 8 + grp) * PADK + k8 + qid;
                uint32_t b0 = __float_as_uint(p[0]);
                uint32_t b1 = __float_as_uint(p[4]);
                mma_tf32(acc[0][nf], af[0], b0, b1);
                mma_tf32(acc[1][nf], af[1], b0, b1);
            }
        }
        __syncthreads();
    }

#pragma unroll
    for (int mf = 0; mf < 2; mf++) {
        int r0 = row0 + wm * 32 + mf * 16 + grp;
#pragma unroll
        for (int nf = 0; nf < 8; nf++) {
            int cg = col0 + wn * 64 + nf * 8 + 2 * qid;
            float bv0 = bias[cg], bv1 = bias[cg + 1];
            float v00 = acc[mf][nf][0] + bv0;
            float v01 = acc[mf][nf][1] + bv1;
            float v10 = acc[mf][nf][2] + bv0;
            float v11 = acc[mf][nf][3] + bv1;
            if (ACT) {
                v00 = 0.5f * v00 * (1.0f + erff(v00 * 0.70710678118654752f));
                v01 = 0.5f * v01 * (1.0f + erff(v01 * 0.70710678118654752f));
                v10 = 0.5f * v10 * (1.0f + erff(v10 * 0.70710678118654752f));
                v11 = 0.5f * v11 * (1.0f + erff(v11 * 0.70710678118654752f));
            }
            *(float2*)&C[(long long)r0 * ldC + cg]       = make_float2(v00, v01);
            *(float2*)&C[(long long)(r0 + 8) * ldC + cg] = make_float2(v10, v11);
        }
    }
}

// ============================ fused flash attention ============================
// One block per (b,h). K[240][68] + Vt[64][244] + per-warp Q stage + per-warp probs.
#define FA_THREADS 512
#define KS_STRIDE  68
#define VT_STRIDE  244
#define FA_KS_FL   (240 * KS_STRIDE)          // 16320
#define FA_VT_FL   (64 * VT_STRIDE)           // 15616
#define FA_QS_FL   (16 * 4 * KS_STRIDE)       // 4352
#define FA_PS_FL   (16 * 4 * 240)             // 15360
#define FA_SMEM    ((FA_KS_FL + FA_VT_FL + FA_QS_FL + FA_PS_FL) * 4)

__global__ __launch_bounds__(FA_THREADS, 1)
void flash_attn(const float* __restrict__ qkv, const int* __restrict__ lengths,
                float* __restrict__ att) {
    extern __shared__ float fs[];
    float* Ks = fs;                       // [240][68]
    float* Vt = Ks + FA_KS_FL;            // [64][244]
    float* Qs = Vt + FA_VT_FL;            // [16][4][68]
    float* Ps = Qs + FA_QS_FL;            // [16][4][240]

    const int bh = blockIdx.x;
    const int b = bh >> 4, h = bh & 15;
    const int tid = threadIdx.x;
    const int w = tid >> 5, lane = tid & 31;
    const int len = lengths[b];
    const float* base = qkv + (long long)b * SEQ * QKVW + h * DHEAD;
    const float scale = 1.0f / 32.0f;

    // stage K (row-major) and V (transposed)
    for (int i = tid; i < 240 * 16; i += FA_THREADS) {
        int s = i >> 4, d4 = i & 15;
        float4 kk = *(const float4*)(base + (long long)s * QKVW + 1024 + d4 * 4);
        float4 vv = *(const float4*)(base + (long long)s * QKVW + 2048 + d4 * 4);
        *(float4*)&Ks[s * KS_STRIDE + d4 * 4] = kk;
        int d = d4 * 4;
        Vt[(d + 0) * VT_STRIDE + s] = vv.x;
        Vt[(d + 1) * VT_STRIDE + s] = vv.y;
        Vt[(d + 2) * VT_STRIDE + s] = vv.z;
        Vt[(d + 3) * VT_STRIDE + s] = vv.w;
    }
    __syncthreads();

    float* Qw = Qs + w * (4 * KS_STRIDE);
    float* Pw = Ps + w * (4 * 240);

    for (int grp = w; grp < 60; grp += 16) {
        const int q0 = grp * 4;
        const int jmax = (q0 + 3) >> 5;

        // stage this group's 4 Q rows
        for (int i = lane; i < 64; i += 32) {
            int r = i >> 4, d4 = i & 15;
            *(float4*)&Qw[r * KS_STRIDE + d4 * 4] =
                *(const float4*)(base + (long long)(q0 + r) * QKVW + d4 * 4);
        }
        __syncwarp();

        // scores: lanes own k = lane + 32j, j <= jmax
        float sc[4][8];
#pragma unroll
        for (int r = 0; r < 4; r++)
#pragma unroll
            for (int j = 0; j < 8; j++) sc[r][j] = 0.f;

#pragma unroll
        for (int d4 = 0; d4 < 16; d4++) {
            float4 qa = *(float4*)&Qw[0 * KS_STRIDE + d4 * 4];
            float4 qb = *(float4*)&Qw[1 * KS_STRIDE + d4 * 4];
            float4 qc = *(float4*)&Qw[2 * KS_STRIDE + d4 * 4];
            float4 qd = *(float4*)&Qw[3 * KS_STRIDE + d4 * 4];
            for (int j = 0; j <= jmax; j++) {
                int k = lane + 32 * j;
                float4 kk = *(float4*)&Ks[k * KS_STRIDE + d4 * 4];
                sc[0][j] += qa.x*kk.x + qa.y*kk.y + qa.z*kk.z + qa.w*kk.w;
                sc[1][j] += qb.x*kk.x + qb.y*kk.y + qb.z*kk.z + qb.w*kk.w;
                sc[2][j] += qc.x*kk.x + qc.y*kk.y + qc.z*kk.z + qc.w*kk.w;
                sc[3][j] += qd.x*kk.x + qd.y*kk.y + qd.z*kk.z + qd.w*kk.w;
            }
        }

        // softmax per row + write probs
#pragma unroll
        for (int r = 0; r < 4; r++) {
            int qr = q0 + r;
            float v[8];
            float m = -1e30f;
#pragma unroll
            for (int j = 0; j < 8; j++) {
                int k = lane + 32 * j;
                v[j] = (k <= qr) ? sc[r][j] * scale : -1e30f;
                m = fmaxf(m, v[j]);
            }
#pragma unroll
            for (int off = 16; off > 0; off >>= 1)
                m = fmaxf(m, __shfl_xor_sync(0xffffffff, m, off));
            float ssum = 0.f;
#pragma unroll
            for (int j = 0; j < 8; j++) {
                v[j] = __expf(v[j] - m);
                ssum += v[j];
            }
#pragma unroll
            for (int off = 16; off > 0; off >>= 1)
                ssum += __shfl_xor_sync(0xffffffff, ssum, off);
            float inv = (qr < len) ? (1.0f / ssum) : 0.0f;   // padded query rows -> 0
#pragma unroll
            for (int j = 0; j < 8; j++) {
                int k = lane + 32 * j;
                if (k < 240) Pw[r * 240 + k] = v[j] * inv;
            }
        }
        __syncwarp();

        // PV: lanes own d = lane, lane+32; k vectorized by 4
        float a00 = 0.f, a01 = 0.f, a10 = 0.f, a11 = 0.f;
        float a20 = 0.f, a21 = 0.f, a30 = 0.f, a31 = 0.f;
        const float4* V0 = (const float4*)&Vt[lane * VT_STRIDE];
        const float4* V1 = (const float4*)&Vt[(lane + 32) * VT_STRIDE];
        const float4* P0 = (const float4*)&Pw[0];
        const float4* P1 = (const float4*)&Pw[240];
        const float4* P2 = (const float4*)&Pw[480];
        const float4* P3 = (const float4*)&Pw[720];
        for (int k4 = 0; k4 <= grp; k4++) {
            float4 v0 = V0[k4], v1 = V1[k4];
            float4 p0 = P0[k4], p1 = P1[k4], p2 = P2[k4], p3 = P3[k4];
            a00 += p0.x*v0.x + p0.y*v0.y + p0.z*v0.z + p0.w*v0.w;
            a01 += p0.x*v1.x + p0.y*v1.y + p0.z*v1.z + p0.w*v1.w;
            a10 += p1.x*v0.x + p1.y*v0.y + p1.z*v0.z + p1.w*v0.w;
            a11 += p1.x*v1.x + p1.y*v1.y + p1.z*v1.z + p1.w*v1.w;
            a20 += p2.x*v0.x + p2.y*v0.y + p2.z*v0.z + p2.w*v0.w;
            a21 += p2.x*v1.x + p2.y*v1.y + p2.z*v1.z + p2.w*v1.w;
            a30 += p3.x*v0.x + p3.y*v0.y + p3.z*v0.z + p3.w*v0.w;
            a31 += p3.x*v1.x + p3.y*v1.y + p3.z*v1.z + p3.w*v1.w;
        }
        float* ob = att + (long long)(b * SEQ + q0) * HID + h * DHEAD;
        ob[0 * HID + lane] = a00;  ob[0 * HID + lane + 32] = a01;
        ob[1 * HID + lane] = a10;  ob[1 * HID + lane + 32] = a11;
        ob[2 * HID + lane] = a20;  ob[2 * HID + lane + 32] = a21;
        ob[3 * HID + lane] = a30;  ob[3 * HID + lane + 32] = a31;
        __syncwarp();
    }
}

// ---------------- embedding: argmax + gather + posenc ----------------
__global__ void embed_kernel(const float* __restrict__ x,
                             const float* __restrict__ w_emb,
                             const float* __restrict__ p_emb,
                             const int*   __restrict__ lengths) {
    int bs = blockIdx.x;
    int b = bs / SEQ, s = bs % SEQ;
    __shared__ int s_tok;
    int tid = threadIdx.x;
    if (tid < 32) {
        const float* xp = x + (long long)bs * NVOCAB;
        float bv = -1e30f; int bi = 0;
        for (int c = tid; c < NVOCAB; c += 32) {
            float v = xp[c];
            if (v > bv) { bv = v; bi = c; }
        }
        for (int off = 16; off > 0; off >>= 1) {
            float ov = __shfl_down_sync(0xffffffff, bv, off);
            int   oi = __shfl_down_sync(0xffffffff, bi, off);
            if (ov > bv || (ov == bv && oi < bi)) { bv = ov; bi = oi; }
        }
        if (tid == 0) s_tok = bi;
    }
    __syncthreads();
    int tok = s_tok;
    float valid = (s < lengths[b]) ? 1.0f : 0.0f;
    const float* we = w_emb + (long long)tok * HID;
    const float* pe = p_emb + (long long)s * HID;
    float* zp = g_z + (long long)bs * HID;
    for (int h = tid; h < HID; h += blockDim.x)
        zp[h] = we[h] * valid + pe[h];
}

// ---------------- residual add + LayerNorm ----------------
__global__ void add_ln_kernel(const float* __restrict__ a, const float* __restrict__ r,
                              const float* __restrict__ sc, const float* __restrict__ bi,
                              float* __restrict__ out) {
    int row = blockIdx.x;
    int tid = threadIdx.x;
    const float* ap = a + (long long)row * HID;
    const float* rp = r + (long long)row * HID;
    float v[4];
    float s = 0.f, sq = 0.f;
#pragma unroll
    for (int j = 0; j < 4; j++) {
        int h = tid + j*256;
        v[j] = ap[h] + rp[h];
        s  += v[j];
        sq += v[j]*v[j];
    }
    __shared__ float red1[8], red2[8];
    for (int off = 16; off > 0; off >>= 1) {
        s  += __shfl_xor_sync(0xffffffff, s,  off);
        sq += __shfl_xor_sync(0xffffffff, sq, off);
    }
    int warp = tid >> 5, lane = tid & 31;
    if (lane == 0) { red1[warp] = s; red2[warp] = sq; }
    __syncthreads();
    if (warp == 0) {
        s  = (lane < 8) ? red1[lane] : 0.f;
        sq = (lane < 8) ? red2[lane] : 0.f;
        for (int off = 4; off > 0; off >>= 1) {
            s  += __shfl_xor_sync(0xffffffff, s,  off);
            sq += __shfl_xor_sync(0xffffffff, sq, off);
        }
        if (lane == 0) { red1[0] = s; red2[0] = sq; }
    }
    __syncthreads();
    float mean = red1[0] * (1.0f / HID);
    float var  = red2[0] * (1.0f / HID) - mean * mean;
    float rstd = rsqrtf(var + 1e-5f);
    float* op = out + (long long)row * HID;
#pragma unroll
    for (int j = 0; j < 4; j++) {
        int h = tid + j*256;
        op[h] = (v[j] - mean) * rstd * sc[h] + bi[h];
    }
}

// ---------------- mean-pool ----------------
__global__ void pool_kernel() {
    int b = blockIdx.y;
    int h = blockIdx.x * 256 + threadIdx.x;
    float s = 0.f;
    const float* zp = g_z + (long long)b * SEQ * HID + h;
    for (int si = 0; si < SEQ; si++)
        s += zp[(long long)si * HID];
    g_pool[b * HID + h] = s * (1.0f / SEQ);
}

// ---------------- classifier head + softmax(4) ----------------
__global__ void head_kernel(const float* __restrict__ Wfc, const float* __restrict__ bfc,
                            float* __restrict__ out) {
    int b = blockIdx.x;
    int tid = threadIdx.x;
    float p[4] = {0.f, 0.f, 0.f, 0.f};
    const float* zp = g_pool + b * HID;
    for (int h = tid; h < HID; h += 256) {
        float zv = zp[h];
#pragma unroll
        for (int c = 0; c < 4; c++) p[c] += zv * Wfc[h*4 + c];
    }
    __shared__ float red[4][256];
#pragma unroll
    for (int c = 0; c < 4; c++) red[c][tid] = p[c];
    __syncthreads();
    for (int str = 128; str > 0; str >>= 1) {
        if (tid < str)
#pragma unroll
            for (int c = 0; c < 4; c++) red[c][tid] += red[c][tid + str];
        __syncthreads();
    }
    if (tid == 0) {
        float l[4];
        float m = -1e30f;
#pragma unroll
        for (int c = 0; c < 4; c++) { l[c] = red[c][0] + bfc[c]; m = fmaxf(m, l[c]); }
        float ssum = 0.f;
#pragma unroll
        for (int c = 0; c < 4; c++) { l[c] = __expf(l[c] - m); ssum += l[c]; }
        float inv = 1.0f / ssum;
#pragma unroll
        for (int c = 0; c < 4; c++) out[b*4 + c] = l[c] * inv;
    }
}

// ---------------- host orchestration ----------------
extern "C" void kernel_launch(void* const* d_in, const int* in_sizes, int n_in,
                              void* d_out, int out_size) {
    const float* x     = (const float*)d_in[0];
    const float* w_emb = (const float*)d_in[1];
    const float* p_emb = (const float*)d_in[2];
    const float* Wq    = (const float*)d_in[3];
    const float* bq    = (const float*)d_in[4];
    const float* Wk    = (const float*)d_in[5];
    const float* bk    = (const float*)d_in[6];
    const float* Wv    = (const float*)d_in[7];
    const float* bv    = (const float*)d_in[8];
    const float* W1    = (const float*)d_in[9];
    const float* b1    = (const float*)d_in[10];
    const float* W2    = (const float*)d_in[11];
    const float* b2    = (const float*)d_in[12];
    const float* ln1_s = (const float*)d_in[13];
    const float* ln1_b = (const float*)d_in[14];
    const float* ln2_s = (const float*)d_in[15];
    const float* ln2_b = (const float*)d_in[16];
    const float* Wfc   = (const float*)d_in[17];
    const float* bfc   = (const float*)d_in[18];
    const int*   lengths = (const int*)d_in[19];
    float* out = (float*)d_out;

    float *pz, *pqkv, *patt, *pz1, *pffh, *pwqkv, *pw12, *pbqkv;
    cudaGetSymbolAddress((void**)&pz,    g_z);
    cudaGetSymbolAddress((void**)&pqkv,  g_qkv);
    cudaGetSymbolAddress((void**)&patt,  g_att);
    cudaGetSymbolAddress((void**)&pz1,   g_z1);
    cudaGetSymbolAddress((void**)&pffh,  g_ffh);
    cudaGetSymbolAddress((void**)&pwqkv, g_wqkv);
    cudaGetSymbolAddress((void**)&pw12,  g_w12);
    cudaGetSymbolAddress((void**)&pbqkv, g_bqkv);

    cudaFuncSetAttribute(gemm_tc<0>, cudaFuncAttributeMaxDynamicSharedMemorySize, GEMM_SMEM);
    cudaFuncSetAttribute(gemm_tc<1>, cudaFuncAttributeMaxDynamicSharedMemorySize, GEMM_SMEM);
    cudaFuncSetAttribute(flash_attn, cudaFuncAttributeMaxDynamicSharedMemorySize, FA_SMEM);

    const long long MAT = (long long)HID * HID;

    // transpose weights into packed layouts
    dim3 tgrid(HID/32, HID/32, NLAYER);
    dim3 tblk(32, 8);
    transpose_kernel<<<tgrid, tblk>>>(Wq, pwqkv + 0*MAT, 3*MAT);
    transpose_kernel<<<tgrid, tblk>>>(Wk, pwqkv + 1*MAT, 3*MAT);
    transpose_kernel<<<tgrid, tblk>>>(Wv, pwqkv + 2*MAT, 3*MAT);
    transpose_kernel<<<tgrid, tblk>>>(W1, pw12  + 0*MAT, 2*MAT);
    transpose_kernel<<<tgrid, tblk>>>(W2, pw12  + 1*MAT, 2*MAT);
    biaspack_kernel<<<(NLAYER*QKVW + 255)/256, 256>>>(bq, bk, bv);

    embed_kernel<<<BS_TOT, 256>>>(x, w_emb, p_emb, lengths);

    dim3 qkv_grid(QKVW/128, BS_TOT/128);   // (24, 60)
    dim3 ff_grid(HID/128, BS_TOT/128);     // (8, 60)

    for (int i = 0; i < NLAYER; i++) {
        long long bOff = (long long)i * HID;
        gemm_tc<0><<<qkv_grid, 256, GEMM_SMEM>>>(pz, pwqkv + (long long)i*3*MAT,
                                                 pbqkv + (long long)i*QKVW, pqkv, QKVW);
        flash_attn<<<NB*NHEAD, FA_THREADS, FA_SMEM>>>(pqkv, lengths, patt);
        add_ln_kernel<<<BS_TOT, 256>>>(pz, patt, ln1_s + bOff, ln1_b + bOff, pz1);
        gemm_tc<1><<<ff_grid, 256, GEMM_SMEM>>>(pz1, pw12 + (long long)i*2*MAT,
                                                b1 + bOff, pffh, HID);
        gemm_tc<0><<<ff_grid, 256, GEMM_SMEM>>>(pffh, pw12 + (long long)i*2*MAT + MAT,
                                                b2 + bOff, patt, HID);
        add_ln_kernel<<<BS_TOT, 256>>>(pz1, patt, ln2_s + bOff, ln2_b + bOff, pz);
    }

    pool_kernel<<<dim3(HID/256, NB), 256>>>();
    head_kernel<<<NB, 256>>>(Wfc, bfc, out);
}